// round 14
// baseline (speedup 1.0000x reference)
#include <cuda_runtime.h>
#include <cstdint>

// Problem constants
#define Bq   64
#define Sq   2048
#define INq  208
#define Hq   100
#define Gq   300      // 3*H gate rows
#define OUTq 98
#define Mq   (Bq * Sq)   // 131072 rows

#define SUB   64          // handoff granularity (steps)
#define NSUB  (Sq / SUB)  // 32
#define NJOB  (Bq * NSUB) // 2048 jobs
#define XGP   304         // padded xg row stride (floats, 16B-aligned)
#define PT    320         // pipeline threads (300 real + 20 pad)

// ---------------------------------------------------------------------------
// Scratch (static __device__ arrays — allocation is forbidden)
// ---------------------------------------------------------------------------
__device__ float g_xg0p[(size_t)Mq * XGP];  // layer-0 input gates (padded)
__device__ float g_xg1p[(size_t)Mq * XGP];  // layer-1 input gates (padded)
__device__ float g_y0  [(size_t)Mq * Hq];   // layer-0 hidden sequence
__device__ float g_y1  [(size_t)Mq * Hq];   // layer-1 hidden sequence
__device__ int   g_fl0[Bq];                 // L0 sub-blocks done per batch
__device__ int   g_fl1[Bq];                 // L1 sub-blocks done per batch
__device__ int   g_flg2[NJOB];              // worker-made xg1 ready
__device__ int   g_cl2[NJOB];               // G2 claim: 0=free 1=worker 2=L1
__device__ int   g_g2ctr, g_g3ctr;

#define FMA2(c, a, b) \
    asm("fma.rn.f32x2 %0, %1, %2, %0;" : "+l"(c) : "l"(a), "l"(b))

__device__ __forceinline__ void cp_async4(uint32_t saddr, const float* gptr) {
    asm volatile("cp.async.ca.shared.global [%0], [%1], 4;"
                 :: "r"(saddr), "l"(gptr));
}
__device__ __forceinline__ void cp_async16(uint32_t saddr, const void* gptr) {
    asm volatile("cp.async.cg.shared.global [%0], [%1], 16;"
                 :: "r"(saddr), "l"(gptr));
}
#define CP_COMMIT()  asm volatile("cp.async.commit_group;" ::: "memory")
#define CP_WAIT(n)   asm volatile("cp.async.wait_group %0;" :: "n"(n) : "memory")

__device__ __forceinline__ float tanh_hw(float x) {
    float y;
    asm("tanh.approx.f32 %0, %1;" : "=f"(y) : "f"(x));
    return y;
}

// ---------------------------------------------------------------------------
// Packed-dot helpers
// ---------------------------------------------------------------------------
__device__ __forceinline__ void load_row100(unsigned long long* wp,
                                            const float* row) {
    const float4* r4 = (const float4*)row;
#pragma unroll
    for (int q = 0; q < 25; q++) {
        const float4 v = __ldg(r4 + q);
        asm("mov.b64 %0, {%1, %2};" : "=l"(wp[2 * q])     : "f"(v.x), "f"(v.y));
        asm("mov.b64 %0, {%1, %2};" : "=l"(wp[2 * q + 1]) : "f"(v.z), "f"(v.w));
    }
}

__device__ __forceinline__ float dot100(const unsigned long long* wp,
                                        const float* vec) {
    const ulonglong2* hp = (const ulonglong2*)vec;
    unsigned long long a0 = 0ull, a1 = 0ull, a2 = 0ull, a3 = 0ull;
#pragma unroll
    for (int q = 0; q < 25; q++) {
        const ulonglong2 hv = hp[q];
        if (q & 1) { FMA2(a1, wp[2 * q], hv.x); FMA2(a3, wp[2 * q + 1], hv.y); }
        else       { FMA2(a0, wp[2 * q], hv.x); FMA2(a2, wp[2 * q + 1], hv.y); }
    }
    unsigned long long s01, s23, ssum;
    asm("add.rn.f32x2 %0, %1, %2;" : "=l"(s01)  : "l"(a0),  "l"(a1));
    asm("add.rn.f32x2 %0, %1, %2;" : "=l"(s23)  : "l"(a2),  "l"(a3));
    asm("add.rn.f32x2 %0, %1, %2;" : "=l"(ssum) : "l"(s01), "l"(s23));
    float lo, hi;
    asm("mov.b64 {%0, %1}, %2;" : "=f"(lo), "=f"(hi) : "l"(ssum));
    return lo + hi;
}

// 104-wide half-row (52 packed regs)
__device__ __forceinline__ void load_row104(unsigned long long* wp,
                                            const float* row) {
    const float4* r4 = (const float4*)row;
#pragma unroll
    for (int q = 0; q < 26; q++) {
        const float4 v = __ldg(r4 + q);
        asm("mov.b64 %0, {%1, %2};" : "=l"(wp[2 * q])     : "f"(v.x), "f"(v.y));
        asm("mov.b64 %0, {%1, %2};" : "=l"(wp[2 * q + 1]) : "f"(v.z), "f"(v.w));
    }
}

__device__ __forceinline__ float dot104(const unsigned long long* wp,
                                        const float* vec) {
    const ulonglong2* hp = (const ulonglong2*)vec;
    unsigned long long a0 = 0ull, a1 = 0ull, a2 = 0ull, a3 = 0ull;
#pragma unroll
    for (int q = 0; q < 26; q++) {
        const ulonglong2 hv = hp[q];
        if (q & 1) { FMA2(a1, wp[2 * q], hv.x); FMA2(a3, wp[2 * q + 1], hv.y); }
        else       { FMA2(a0, wp[2 * q], hv.x); FMA2(a2, wp[2 * q + 1], hv.y); }
    }
    unsigned long long s01, s23, ssum;
    asm("add.rn.f32x2 %0, %1, %2;" : "=l"(s01)  : "l"(a0),  "l"(a1));
    asm("add.rn.f32x2 %0, %1, %2;" : "=l"(s23)  : "l"(a2),  "l"(a3));
    asm("add.rn.f32x2 %0, %1, %2;" : "=l"(ssum) : "l"(s01), "l"(s23));
    float lo, hi;
    asm("mov.b64 {%0, %1}, %2;" : "=f"(lo), "=f"(hi) : "l"(ssum));
    return lo + hi;
}

// ---------------------------------------------------------------------------
// Flag reset
// ---------------------------------------------------------------------------
__global__ void zero_flags() {
    const int g = blockIdx.x * blockDim.x + threadIdx.x;
    const int stride = gridDim.x * blockDim.x;
    for (int i = g; i < NJOB; i += stride) { g_cl2[i] = 0; g_flg2[i] = 0; }
    if (g < Bq) { g_fl0[g] = 0; g_fl1[g] = 0; }
    if (g == Bq) { g_g2ctr = 0; g_g3ctr = 0; }
}

// ---------------------------------------------------------------------------
// G1: xg0p[b,t,:] = seq[b,t,:] @ w_ih_l0^T + b_ih_l0  (padded XGP rows).
// Grid 2048 = (b,sub); 320 threads (2.5 warps/SMSP -> FMA2 rt-3 bound);
// two 104-wide K-half passes, SMEM accumulate, one gmem store pass.
// ---------------------------------------------------------------------------
__global__ __launch_bounds__(PT, 1) void g1_kernel(
    const float* __restrict__ seq,
    const float* __restrict__ w_ih, const float* __restrict__ b_ih)
{
    extern __shared__ __align__(16) float dyn[];
    float* seqstage = dyn;                   // [SUB*INq]
    float* xg_sub   = dyn + SUB * INq;       // [SUB][XGP]

    const int tid = threadIdx.x;
    const int j   = blockIdx.x;
    const int b   = j & (Bq - 1);
    const int t0  = (j >> 6) * SUB;
    const int wr  = min(tid, Gq - 1);
    const int col = min(tid, XGP - 1);
    const uint32_t dyn_sa = (uint32_t)__cvta_generic_to_shared(dyn);

    const float4* src = (const float4*)(seq + ((size_t)b * Sq + t0) * INq);
    for (int i = tid; i < SUB * INq / 4; i += PT)
        cp_async16(dyn_sa + i * 16, src + i);
    CP_COMMIT(); CP_WAIT(0);
    __syncthreads();

    unsigned long long wp[52];
    load_row104(wp, w_ih + wr * INq);
#pragma unroll 2
    for (int tt = 0; tt < SUB; tt++)
        xg_sub[tt * XGP + col] = dot104(wp, seqstage + tt * INq);

    load_row104(wp, w_ih + wr * INq + 104);
    const float bias = b_ih[wr];
#pragma unroll 2
    for (int tt = 0; tt < SUB; tt++)
        xg_sub[tt * XGP + col] += dot104(wp, seqstage + tt * INq + 104) + bias;
    __syncthreads();

    float4*       dst4 = (float4*)(g_xg0p + ((size_t)b * Sq + t0) * XGP);
    const float4* s4   = (const float4*)xg_sub;
    for (int i = tid; i < SUB * XGP / 4; i += PT)
        dst4[i] = s4[i];
}

// ---------------------------------------------------------------------------
// Scan SMEM (all arrays indexable by all PT threads -> guard-free matvec)
// ---------------------------------------------------------------------------
struct GruSmem {
    float h[2][128];        // units 0..99 real
    float hg[PT];           // rows 0..299 real
    float ring[4][PT];      // xg staging ring
};

// gate nonlinearity via HW tanh
__device__ __forceinline__ void gate_math(
    int t, int cur, int tid, int jc, GruSmem* s,
    const float* __restrict__ xgp, float* __restrict__ y_b)
{
    const float xr = xgp[jc], xz = xgp[Hq + jc], xn = xgp[2 * Hq + jc];
    const float hr = s->hg[jc];
    const float hz = s->hg[Hq + jc];
    const float hn = s->hg[2 * Hq + jc];
    const float hprev = s->h[cur][jc];
    const float r  = 0.5f * tanh_hw(0.5f * (xr + hr)) + 0.5f;
    const float z  = 0.5f * tanh_hw(0.5f * (xz + hz)) + 0.5f;
    const float nt = tanh_hw(xn + r * hn);
    const float hnew = (1.f - z) * nt + z * hprev;
    s->h[cur ^ 1][tid] = hnew;
    if (tid < Hq) y_b[(size_t)t * Hq + tid] = hnew;
}

// Ring-streaming GRU step (xg from gmem, padded XGP stride)
__device__ __forceinline__ void gru_step_ring(
    int t, int cur, int tid, int jc, int wr,
    GruSmem* s, uint32_t ring_sa,
    const unsigned long long* wp, float bhh,
    const float* __restrict__ xg_base, int rmax,
    float* __restrict__ y_b)
{
    const int r = min(t + 3, rmax);
    cp_async4(ring_sa + (((t + 3) & 3) * PT + tid) * 4,
              xg_base + (size_t)r * XGP + wr);
    CP_COMMIT();

    s->hg[tid] = dot100(wp, s->h[cur]) + bhh;    // uniform, all PT threads
    __syncthreads();                             // A: hg complete

    if (tid < 128) gate_math(t, cur, tid, jc, s, &s->ring[t & 3][0], y_b);
    CP_WAIT(2);                                  // ring slot t+1 landed
    __syncthreads();                             // B: publish
}

// SMEM-xg GRU step (L1 inline path)
__device__ __forceinline__ void gru_step_smem(
    int t, int cur, int tid, int jc,
    GruSmem* s,
    const unsigned long long* wp, float bhh,
    const float* __restrict__ xg_sub,
    float* __restrict__ y_b)
{
    s->hg[tid] = dot100(wp, s->h[cur]) + bhh;
    __syncthreads();                             // A
    if (tid < 128)
        gate_math(t, cur, tid, jc, s, xg_sub + (t & (SUB - 1)) * XGP, y_b);
    __syncthreads();                             // B
}

__device__ __forceinline__ void ring_prologue(
    uint32_t ring_sa, const float* xg_base, int t0, int rmax,
    int tid, int wr)
{
#pragma unroll
    for (int p = 0; p < 3; p++) {
        cp_async4(ring_sa + (((t0 + p) & 3) * PT + tid) * 4,
                  xg_base + (size_t)min(t0 + p, rmax) * XGP + wr);
        CP_COMMIT();
    }
    CP_WAIT(2);
    __syncthreads();
}

__device__ __forceinline__ void wait_flag(volatile int* f, int target, int tid) {
    if (tid == 0) {
        while (*f < target) __nanosleep(128);
    }
    __syncthreads();
    __threadfence();                             // acquire
}

// ---------------------------------------------------------------------------
// Persistent pipeline: 148 CTAs x PT threads (all co-resident).
//   CTA 0..63    : L0 scan (ring from g_xg0p), flags fl0 -> G2 -> G3
//   CTA 64..127  : L1: per sub claim-or-consume G2 -> G3
//   CTA 128..147 : G2 workers -> G3 pool
// Dyn SMEM 103424B: [ystage 64*100 | xg_sub 64*304]
// ---------------------------------------------------------------------------
__global__ __launch_bounds__(PT, 1) void pipeline_kernel(
    const float* __restrict__ w_hh_l0, const float* __restrict__ b_hh_l0,
    const float* __restrict__ w_ih_l1, const float* __restrict__ b_ih_l1,
    const float* __restrict__ w_hh_l1, const float* __restrict__ b_hh_l1,
    const float* __restrict__ w_out,   const float* __restrict__ b_out,
    const float* __restrict__ h0,      float* __restrict__ out)
{
    extern __shared__ __align__(16) float dyn[];
    __shared__ __align__(16) GruSmem s;
    __shared__ int js, cls;

    const int tid  = threadIdx.x;
    const int role = blockIdx.x;
    const int wr   = min(tid, Gq - 1);
    const int jc   = min(tid, Hq - 1);
    const int col  = min(tid, XGP - 1);
    const uint32_t ring_sa = (uint32_t)__cvta_generic_to_shared(&s.ring[0][0]);
    const uint32_t dyn_sa  = (uint32_t)__cvta_generic_to_shared(dyn);
    float* ystage = dyn;                     // [SUB*Hq]
    float* xg_sub = dyn + SUB * Hq;          // [SUB][XGP]

    unsigned long long wp[50];
    bool help_g2 = (role >= 2 * Bq);

    if (role < Bq) {
        // ---------------- L0 scan (xg0p fully ready) ----------------
        const int b = role;
        const float* xg0p_b = g_xg0p + (size_t)b * Sq * XGP;
        float*       y_b    = g_y0   + (size_t)b * Sq * Hq;
        if (tid < Hq) s.h[0][tid] = h0[b * Hq + tid];
        __syncthreads();

        load_row100(wp, w_hh_l0 + wr * Hq);
        const float bhh = b_hh_l0[wr];

        ring_prologue(ring_sa, xg0p_b, 0, Sq - 1, tid, wr);

        for (int t = 0; t < Sq; t += 2) {
            gru_step_ring(t,     0, tid, jc, wr, &s, ring_sa, wp, bhh,
                          xg0p_b, Sq - 1, y_b);
            gru_step_ring(t + 1, 1, tid, jc, wr, &s, ring_sa, wp, bhh,
                          xg0p_b, Sq - 1, y_b);
            if (((t + 2) & (SUB - 1)) == 0) {
                __threadfence();
                __syncthreads();
                if (tid == 0) atomicExch(g_fl0 + b, (t + 2) / SUB);
            }
        }
        help_g2 = true;
    } else if (role < 2 * Bq) {
        // ---------------- L1: claim-or-consume G2, then scan ----------------
        const int b = role - Bq;
        const float* y0_b   = g_y0   + (size_t)b * Sq * Hq;
        float*       y1_b   = g_y1   + (size_t)b * Sq * Hq;
        const float* xg1p_b = g_xg1p + (size_t)b * Sq * XGP;
        if (tid < Hq) s.h[0][tid] = h0[Bq * Hq + b * Hq + tid];
        __syncthreads();

        load_row100(wp, w_hh_l1 + wr * Hq);
        const float bhh = b_hh_l1[wr];

        for (int sub = 0; sub < NSUB; sub++) {
            const int t0 = sub * SUB;
            const int j  = sub * Bq + b;

            if (tid == 0) cls = atomicCAS(&g_cl2[j], 0, 2);
            __syncthreads();
            const int owner = cls;
            __syncthreads();

            if (owner == 0) {
                // inline: stage y0 -> G2 into SMEM -> scan from SMEM
                wait_flag(g_fl0 + b, sub + 1, tid);
                const float4* src = (const float4*)(y0_b + (size_t)t0 * Hq);
                for (int i = tid; i < SUB * Hq / 4; i += PT)
                    cp_async16(dyn_sa + i * 16, src + i);
                CP_COMMIT(); CP_WAIT(0);
                __syncthreads();

                load_row100(wp, w_ih_l1 + wr * Hq);
                const float bih = b_ih_l1[wr];
#pragma unroll 2
                for (int tt = 0; tt < SUB; tt++)
                    xg_sub[tt * XGP + col] = dot100(wp, ystage + tt * Hq) + bih;
                __syncthreads();

                load_row100(wp, w_hh_l1 + wr * Hq);
                for (int t = t0; t < t0 + SUB; t += 2) {
                    gru_step_smem(t,     0, tid, jc, &s, wp, bhh, xg_sub, y1_b);
                    gru_step_smem(t + 1, 1, tid, jc, &s, wp, bhh, xg_sub, y1_b);
                }
            } else {
                // consume: ring-stream worker-made xg1p
                wait_flag(g_flg2 + j, 1, tid);
                ring_prologue(ring_sa, xg1p_b, t0, t0 + SUB - 1, tid, wr);
                for (int t = t0; t < t0 + SUB; t += 2) {
                    gru_step_ring(t,     0, tid, jc, wr, &s, ring_sa, wp, bhh,
                                  xg1p_b, t0 + SUB - 1, y1_b);
                    gru_step_ring(t + 1, 1, tid, jc, wr, &s, ring_sa, wp, bhh,
                                  xg1p_b, t0 + SUB - 1, y1_b);
                }
            }
            __threadfence();
            __syncthreads();
            if (tid == 0) atomicExch(g_fl1 + b, sub + 1);
        }
    }

    // ---------------- G2 queue (workers + finished L0 CTAs) ----------------
    if (help_g2) {
        load_row100(wp, w_ih_l1 + wr * Hq);
        const float bih = b_ih_l1[wr];

        for (;;) {
            if (tid == 0) js = atomicAdd(&g_g2ctr, 1);
            __syncthreads();
            const int j = js;
            __syncthreads();
            if (j >= NJOB) break;

            if (tid == 0) cls = atomicCAS(&g_cl2[j], 0, 1);
            __syncthreads();
            const int got = cls;
            __syncthreads();
            if (got != 0) continue;              // L1 already inlined it

            const int b = j & (Bq - 1), sub = j >> 6, t0 = sub * SUB;
            wait_flag(g_fl0 + b, sub + 1, tid);

            const float4* src = (const float4*)(g_y0 +
                                ((size_t)b * Sq + t0) * Hq);
            for (int i = tid; i < SUB * Hq / 4; i += PT)
                cp_async16(dyn_sa + i * 16, src + i);
            CP_COMMIT(); CP_WAIT(0);
            __syncthreads();

            float* dst = g_xg1p + ((size_t)b * Sq + t0) * XGP + wr;
#pragma unroll 2
            for (int tt = 0; tt < SUB; tt++) {
                const float v = dot100(wp, dyn + tt * Hq) + bih;
                if (tid < Gq) dst[(size_t)tt * XGP] = v;
            }
            __threadfence();
            __syncthreads();
            if (tid == 0) atomicExch(&g_flg2[j], 1);
            __syncthreads();                     // protect dyn (WAR)
        }
    }

    // ---------------- G3 pool: out = y1 @ w_out^T + b_out ----------------
    {
        const int nidx = tid % 160;              // 2 groups of 160
        const int tq   = tid / 160;              // 0..1
        const int nr   = min(nidx, OUTq - 1);
        load_row100(wp, w_out + nr * Hq);
        const float bo = b_out[nr];

        for (;;) {
            if (tid == 0) js = atomicAdd(&g_g3ctr, 1);
            __syncthreads();
            const int j = js;
            __syncthreads();
            if (j >= Bq * 16) break;             // 1024 jobs of 128 steps
            const int b   = j & (Bq - 1);
            const int blk = j >> 6;              // 0..15

            wait_flag(g_fl1 + b, 2 * blk + 2, tid);

            const float4* src = (const float4*)(g_y1 +
                                ((size_t)b * Sq + blk * 128) * Hq);
            for (int i = tid; i < 128 * Hq / 4; i += PT)
                cp_async16(dyn_sa + i * 16, src + i);
            CP_COMMIT(); CP_WAIT(0);
            __syncthreads();

            if (nidx < OUTq) {
                float* ob = out + ((size_t)b * Sq + blk * 128) * OUTq;
                for (int tt = tq; tt < 128; tt += 2)
                    ob[(size_t)tt * OUTq + nidx] = dot100(wp, dyn + tt * Hq) + bo;
            }
            __syncthreads();                     // protect stage (WAR)
        }
    }
}

// ---------------------------------------------------------------------------
// Launch: zero_flags -> g1 (320-thread dot kernel) -> persistent pipeline.
// One stream, graph-capturable, no allocations.
// ---------------------------------------------------------------------------
extern "C" void kernel_launch(void* const* d_in, const int* in_sizes, int n_in,
                              void* d_out, int out_size)
{
    (void)in_sizes; (void)n_in; (void)out_size;
    const float* seq     = (const float*)d_in[0];
    const float* h0      = (const float*)d_in[1];   // [2][B][H]
    const float* w_ih_l0 = (const float*)d_in[2];
    const float* w_hh_l0 = (const float*)d_in[3];
    const float* b_ih_l0 = (const float*)d_in[4];
    const float* b_hh_l0 = (const float*)d_in[5];
    const float* w_ih_l1 = (const float*)d_in[6];
    const float* w_hh_l1 = (const float*)d_in[7];
    const float* b_ih_l1 = (const float*)d_in[8];
    const float* b_hh_l1 = (const float*)d_in[9];
    const float* w_out   = (const float*)d_in[10];
    const float* b_out   = (const float*)d_in[11];
    float* out = (float*)d_out;

    const int G1_BYTES   = (SUB * INq + SUB * XGP) * 4;  // 131072
    const int PIPE_BYTES = (SUB * Hq + SUB * XGP) * 4;   // 103424
    cudaFuncSetAttribute(g1_kernel,
                         cudaFuncAttributeMaxDynamicSharedMemorySize, G1_BYTES);
    cudaFuncSetAttribute(pipeline_kernel,
                         cudaFuncAttributeMaxDynamicSharedMemorySize, PIPE_BYTES);

    zero_flags<<<16, 256>>>();

    g1_kernel<<<NJOB, PT, G1_BYTES>>>(seq, w_ih_l0, b_ih_l0);

    pipeline_kernel<<<148, PT, PIPE_BYTES>>>(
        w_hh_l0, b_hh_l0,
        w_ih_l1, b_ih_l1, w_hh_l1, b_hh_l1,
        w_out, b_out, h0, out);
}

// round 15
// speedup vs baseline: 1.5654x; 1.5654x over previous
#include <cuda_runtime.h>
#include <cstdint>

// Problem constants
#define Bq   64
#define Sq   2048
#define INq  208
#define Hq   100
#define Gq   300      // 3*H gate rows
#define OUTq 98
#define Mq   (Bq * Sq)   // 131072 rows

#define SUB   64          // handoff granularity (steps)
#define NSUB  (Sq / SUB)  // 32
#define NJOB2 (Bq * NSUB) // 2048 G2 jobs
#define XGP   304         // padded xg1 row stride (floats, 16B-aligned)
#define PT    320         // pipeline threads (300 real + 20 pad)

// ---------------------------------------------------------------------------
// Scratch (static __device__ arrays — allocation is forbidden)
// ---------------------------------------------------------------------------
__device__ float g_xg0 [(size_t)Mq * Gq];   // layer-0 input gates (G1 out)
__device__ float g_xg1p[(size_t)Mq * XGP];  // layer-1 input gates, padded rows
__device__ float g_y0  [(size_t)Mq * Hq];   // layer-0 hidden sequence
__device__ float g_y1  [(size_t)Mq * Hq];   // layer-1 hidden sequence
__device__ int   g_fl0[Bq];                 // L0 sub-blocks done per batch
__device__ int   g_fl1[Bq];                 // L1 sub-blocks done per batch
__device__ int   g_fl2[NJOB2];              // per-job xg1 ready
__device__ int   g_claim[NJOB2];            // 0=free 1=worker 2=L1-inline
__device__ int   g_jobctr;                  // G3 job counter
__device__ int   g_g2ctr;                   // G2 worker job counter

#define FMA2(c, a, b) \
    asm("fma.rn.f32x2 %0, %1, %2, %0;" : "+l"(c) : "l"(a), "l"(b))

__device__ __forceinline__ void cp_async4(uint32_t saddr, const float* gptr) {
    asm volatile("cp.async.ca.shared.global [%0], [%1], 4;"
                 :: "r"(saddr), "l"(gptr));
}
__device__ __forceinline__ void cp_async16(uint32_t saddr, const void* gptr) {
    asm volatile("cp.async.cg.shared.global [%0], [%1], 16;"
                 :: "r"(saddr), "l"(gptr));
}
#define CP_COMMIT()  asm volatile("cp.async.commit_group;" ::: "memory")
#define CP_WAIT(n)   asm volatile("cp.async.wait_group %0;" :: "n"(n) : "memory")

__device__ __forceinline__ float tanh_hw(float x) {
    float y;
    asm("tanh.approx.f32 %0, %1;" : "=f"(y) : "f"(x));
    return y;
}

// ---------------------------------------------------------------------------
// Packed-dot helpers
// ---------------------------------------------------------------------------
__device__ __forceinline__ void load_row100(unsigned long long* wp,
                                            const float* row) {
    const float4* r4 = (const float4*)row;
#pragma unroll
    for (int q = 0; q < 25; q++) {
        const float4 v = __ldg(r4 + q);
        asm("mov.b64 %0, {%1, %2};" : "=l"(wp[2 * q])     : "f"(v.x), "f"(v.y));
        asm("mov.b64 %0, {%1, %2};" : "=l"(wp[2 * q + 1]) : "f"(v.z), "f"(v.w));
    }
}

__device__ __forceinline__ float dot100(const unsigned long long* wp,
                                        const float* vec) {
    const ulonglong2* hp = (const ulonglong2*)vec;
    unsigned long long a0 = 0ull, a1 = 0ull, a2 = 0ull, a3 = 0ull;
#pragma unroll
    for (int q = 0; q < 25; q++) {
        const ulonglong2 hv = hp[q];
        if (q & 1) { FMA2(a1, wp[2 * q], hv.x); FMA2(a3, wp[2 * q + 1], hv.y); }
        else       { FMA2(a0, wp[2 * q], hv.x); FMA2(a2, wp[2 * q + 1], hv.y); }
    }
    unsigned long long s01, s23, ssum;
    asm("add.rn.f32x2 %0, %1, %2;" : "=l"(s01)  : "l"(a0),  "l"(a1));
    asm("add.rn.f32x2 %0, %1, %2;" : "=l"(s23)  : "l"(a2),  "l"(a3));
    asm("add.rn.f32x2 %0, %1, %2;" : "=l"(ssum) : "l"(s01), "l"(s23));
    float lo, hi;
    asm("mov.b64 {%0, %1}, %2;" : "=f"(lo), "=f"(hi) : "l"(ssum));
    return lo + hi;
}

__device__ __forceinline__ void load_row208(unsigned long long* wp,
                                            const float* row) {
    const float4* r4 = (const float4*)row;
#pragma unroll
    for (int q = 0; q < 52; q++) {
        const float4 v = __ldg(r4 + q);
        asm("mov.b64 %0, {%1, %2};" : "=l"(wp[2 * q])     : "f"(v.x), "f"(v.y));
        asm("mov.b64 %0, {%1, %2};" : "=l"(wp[2 * q + 1]) : "f"(v.z), "f"(v.w));
    }
}

__device__ __forceinline__ float dot208(const unsigned long long* wp,
                                        const float* vec) {
    const ulonglong2* hp = (const ulonglong2*)vec;
    unsigned long long a0 = 0ull, a1 = 0ull, a2 = 0ull, a3 = 0ull;
#pragma unroll
    for (int q = 0; q < 52; q++) {
        const ulonglong2 hv = hp[q];
        if (q & 1) { FMA2(a1, wp[2 * q], hv.x); FMA2(a3, wp[2 * q + 1], hv.y); }
        else       { FMA2(a0, wp[2 * q], hv.x); FMA2(a2, wp[2 * q + 1], hv.y); }
    }
    unsigned long long s01, s23, ssum;
    asm("add.rn.f32x2 %0, %1, %2;" : "=l"(s01)  : "l"(a0),  "l"(a1));
    asm("add.rn.f32x2 %0, %1, %2;" : "=l"(s23)  : "l"(a2),  "l"(a3));
    asm("add.rn.f32x2 %0, %1, %2;" : "=l"(ssum) : "l"(s01), "l"(s23));
    float lo, hi;
    asm("mov.b64 {%0, %1}, %2;" : "=f"(lo), "=f"(hi) : "l"(ssum));
    return lo + hi;
}

// ---------------------------------------------------------------------------
// G1: xg0 = seq @ w_ih_l0^T + b_ih_l0 (R12-proven: 160 threads, reg-resident
// 208-wide rows, two 150-row passes). Also resets all pipeline flags.
// ---------------------------------------------------------------------------
__global__ __launch_bounds__(160, 1) void g1_kernel(
    const float* __restrict__ seq,
    const float* __restrict__ w_ih, const float* __restrict__ b_ih)
{
    extern __shared__ __align__(16) float st[];   // [SUB][208]
    const int tid = threadIdx.x;
    const int j   = blockIdx.x;
    const int b   = j & (Bq - 1);
    const int sub = j >> 6;
    const int t0  = sub * SUB;

    if (tid == 0) { g_claim[j] = 0; g_fl2[j] = 0; }
    if (j == 0) {
        if (tid < Bq) { g_fl0[tid] = 0; g_fl1[tid] = 0; }
        if (tid == 64) { g_jobctr = 0; g_g2ctr = 0; }
    }

    const uint32_t st_sa = (uint32_t)__cvta_generic_to_shared(st);
    const float4* src = (const float4*)(seq + ((size_t)b * Sq + t0) * INq);
    for (int i = tid; i < SUB * INq / 4; i += 160)
        cp_async16(st_sa + i * 16, src + i);
    CP_COMMIT(); CP_WAIT(0);
    __syncthreads();

    unsigned long long wp[104];
#pragma unroll
    for (int pass = 0; pass < 2; pass++) {
        const int r = pass * 150 + min(tid, 149);
        load_row208(wp, w_ih + r * INq);
        const float bias = b_ih[r];
        float* dst = g_xg0 + ((size_t)b * Sq + t0) * Gq + r;
#pragma unroll 2
        for (int tt = 0; tt < SUB; tt++) {
            const float v = dot208(wp, st + tt * INq) + bias;
            if (tid < 150) dst[(size_t)tt * Gq] = v;
        }
    }
}

// ---------------------------------------------------------------------------
// Scan SMEM (all arrays indexable by all PT threads -> guard-free matvec)
// ---------------------------------------------------------------------------
struct GruSmem {
    float h[2][128];        // units 0..99 real
    float hg[PT];           // rows 0..299 real
    float ring[4][PT];      // xg staging ring
};

// gate nonlinearity via HW tanh (validated: rel_err ~5.7e-6)
__device__ __forceinline__ void gate_math(
    int t, int cur, int tid, int jc, GruSmem* s,
    const float* __restrict__ xgp, float* __restrict__ y_b)
{
    const float xr = xgp[jc], xz = xgp[Hq + jc], xn = xgp[2 * Hq + jc];
    const float hr = s->hg[jc];
    const float hz = s->hg[Hq + jc];
    const float hn = s->hg[2 * Hq + jc];
    const float hprev = s->h[cur][jc];
    const float r  = 0.5f * tanh_hw(0.5f * (xr + hr)) + 0.5f;
    const float z  = 0.5f * tanh_hw(0.5f * (xz + hz)) + 0.5f;
    const float nt = tanh_hw(xn + r * hn);
    const float hnew = (1.f - z) * nt + z * hprev;
    s->h[cur ^ 1][tid] = hnew;
    if (tid < Hq) y_b[(size_t)t * Hq + tid] = hnew;
}

// Ring-streaming GRU step: xg prefetched from gmem (stride/clamp params let
// L0 stream xg0 rows and L1 stream padded xg1p rows within a sub).
__device__ __forceinline__ void gru_step_ring(
    int t, int cur, int tid, int jc, int wr,
    GruSmem* s, uint32_t ring_sa,
    const unsigned long long* wp, float bhh,
    const float* __restrict__ xg_base, int stride, int rmax,
    float* __restrict__ y_b)
{
    const int r = min(t + 3, rmax);
    cp_async4(ring_sa + (((t + 3) & 3) * PT + tid) * 4,
              xg_base + (size_t)r * stride + wr);
    CP_COMMIT();

    s->hg[tid] = dot100(wp, s->h[cur]) + bhh;    // uniform, all PT threads
    __syncthreads();                             // A: hg complete

    if (tid < 128) gate_math(t, cur, tid, jc, s, &s->ring[t & 3][0], y_b);
    CP_WAIT(2);                                  // ring slot t+1 landed
    __syncthreads();                             // B: publish
}

// SMEM-xg GRU step (L1 inline path; xg_sub rows padded to XGP)
__device__ __forceinline__ void gru_step_smem(
    int t, int cur, int tid, int jc,
    GruSmem* s,
    const unsigned long long* wp, float bhh,
    const float* __restrict__ xg_sub,
    float* __restrict__ y_b)
{
    s->hg[tid] = dot100(wp, s->h[cur]) + bhh;
    __syncthreads();                             // A
    if (tid < 128)
        gate_math(t, cur, tid, jc, s, xg_sub + (t & (SUB - 1)) * XGP, y_b);
    __syncthreads();                             // B
}

// stage 3 ring rows t0..t0+2 (clamped); leaves <=2 groups pending
__device__ __forceinline__ void ring_prologue(
    uint32_t ring_sa, const float* xg_base, int stride, int t0, int rmax,
    int tid, int wr)
{
#pragma unroll
    for (int p = 0; p < 3; p++) {
        cp_async4(ring_sa + (((t0 + p) & 3) * PT + tid) * 4,
                  xg_base + (size_t)min(t0 + p, rmax) * stride + wr);
        CP_COMMIT();
    }
    CP_WAIT(2);
    __syncthreads();
}

__device__ __forceinline__ void wait_flag(volatile int* f, int target, int tid) {
    if (tid == 0) {
        while (*f < target) __nanosleep(128);
    }
    __syncthreads();
    __threadfence();                             // acquire
}

// ---------------------------------------------------------------------------
// Persistent pipeline: 148 CTAs x PT threads (all co-resident).
//   CTA 0..63    : L0 scan (ring from g_xg0), flags fl0 per 64 steps,
//                  then G2 queue, then G3 pool
//   CTA 64..127  : L1: per sub claim-or-consume (inline G2 in SMEM, or
//                  ring-stream worker-made xg1p), then G3 pool
//   CTA 128..147 : G2 workers -> G3 pool
// ---------------------------------------------------------------------------
__global__ __launch_bounds__(PT, 1) void pipeline_kernel(
    const float* __restrict__ w_hh_l0, const float* __restrict__ b_hh_l0,
    const float* __restrict__ w_ih_l1, const float* __restrict__ b_ih_l1,
    const float* __restrict__ w_hh_l1, const float* __restrict__ b_hh_l1,
    const float* __restrict__ w_out,   const float* __restrict__ b_out,
    const float* __restrict__ h0,      float* __restrict__ out)
{
    extern __shared__ __align__(16) float dyn[];
    __shared__ __align__(16) GruSmem s;
    __shared__ int js, cls;

    const int tid  = threadIdx.x;
    const int role = blockIdx.x;
    const int wr   = min(tid, Gq - 1);
    const int jc   = min(tid, Hq - 1);
    const uint32_t ring_sa = (uint32_t)__cvta_generic_to_shared(&s.ring[0][0]);
    const uint32_t dyn_sa  = (uint32_t)__cvta_generic_to_shared(dyn);

    unsigned long long wp[50];
    bool do_g2_queue = (role >= 2 * Bq);   // workers start on G2 immediately

    if (role < Bq) {
        // ---------------- L0 scan ----------------
        const int b = role;
        load_row100(wp, w_hh_l0 + wr * Hq);
        const float bhh = b_hh_l0[wr];
        if (tid < Hq) s.h[0][tid] = h0[b * Hq + tid];
        const float* xg_b = g_xg0 + (size_t)b * Sq * Gq;
        float*       y_b  = g_y0  + (size_t)b * Sq * Hq;

        ring_prologue(ring_sa, xg_b, Gq, 0, Sq - 1, tid, wr);

        for (int t = 0; t < Sq; t += 2) {
            gru_step_ring(t,     0, tid, jc, wr, &s, ring_sa, wp, bhh,
                          xg_b, Gq, Sq - 1, y_b);
            gru_step_ring(t + 1, 1, tid, jc, wr, &s, ring_sa, wp, bhh,
                          xg_b, Gq, Sq - 1, y_b);
            if (((t + 2) & (SUB - 1)) == 0) {
                __threadfence();
                __syncthreads();
                if (tid == 0) atomicExch(g_fl0 + b, (t + 2) / SUB);
            }
        }
        do_g2_queue = true;                      // help finish G2, then G3
    } else if (role < 2 * Bq) {
        // ---------------- L1 ----------------
        const int b = role - Bq;
        const float* y0_b  = g_y0 + (size_t)b * Sq * Hq;
        float*       y1_b  = g_y1 + (size_t)b * Sq * Hq;
        const float* xgp_b = g_xg1p + (size_t)b * Sq * XGP;
        float* ystage = dyn;                     // [SUB*Hq]
        float* xg_sub = dyn + SUB * Hq;          // [SUB][XGP]
        const int col = min(tid, XGP - 1);
        if (tid < Hq) s.h[0][tid] = h0[Bq * Hq + b * Hq + tid];
        __syncthreads();

        // preload recurrent weights once; inline path reloads around G2
        load_row100(wp, w_hh_l1 + wr * Hq);
        float bhh = b_hh_l1[wr];

        for (int sub = 0; sub < NSUB; sub++) {
            const int t0 = sub * SUB;
            const int j  = sub * Bq + b;

            if (tid == 0) cls = atomicCAS(&g_claim[j], 0, 2);
            __syncthreads();
            const int owner = cls;
            __syncthreads();

            if (owner == 0) {
                // inline: stage y0 -> compute G2 into SMEM -> scan from SMEM
                wait_flag(g_fl0 + b, sub + 1, tid);
                const float4* src = (const float4*)(y0_b + (size_t)t0 * Hq);
                for (int i = tid; i < SUB * Hq / 4; i += PT)
                    cp_async16(dyn_sa + i * 16, src + i);
                CP_COMMIT(); CP_WAIT(0);
                __syncthreads();

                load_row100(wp, w_ih_l1 + wr * Hq);
                const float bih = b_ih_l1[wr];
#pragma unroll 2
                for (int tt = 0; tt < SUB; tt++)
                    xg_sub[tt * XGP + col] = dot100(wp, ystage + tt * Hq) + bih;
                __syncthreads();

                load_row100(wp, w_hh_l1 + wr * Hq);
                for (int t = t0; t < t0 + SUB; t += 2) {
                    gru_step_smem(t,     0, tid, jc, &s, wp, bhh, xg_sub, y1_b);
                    gru_step_smem(t + 1, 1, tid, jc, &s, wp, bhh, xg_sub, y1_b);
                }
            } else {
                // consume: ring-stream worker-made xg1p (no block copy)
                wait_flag(g_fl2 + j, 1, tid);
                ring_prologue(ring_sa, xgp_b, XGP, t0, t0 + SUB - 1, tid, wr);
                for (int t = t0; t < t0 + SUB; t += 2) {
                    gru_step_ring(t,     0, tid, jc, wr, &s, ring_sa, wp, bhh,
                                  xgp_b, XGP, t0 + SUB - 1, y1_b);
                    gru_step_ring(t + 1, 1, tid, jc, wr, &s, ring_sa, wp, bhh,
                                  xgp_b, XGP, t0 + SUB - 1, y1_b);
                }
            }
            __threadfence();
            __syncthreads();
            if (tid == 0) atomicExch(g_fl1 + b, sub + 1);
        }
    }

    // ---------------- G2 queue (workers from start; L0 CTAs after scan) ----
    if (do_g2_queue) {
        load_row100(wp, w_ih_l1 + wr * Hq);
        const float bih = b_ih_l1[wr];

        for (;;) {
            if (tid == 0) js = atomicAdd(&g_g2ctr, 1);
            __syncthreads();
            const int j = js;
            __syncthreads();
            if (j >= NJOB2) break;

            if (tid == 0) cls = atomicCAS(&g_claim[j], 0, 1);
            __syncthreads();
            const int got = cls;
            __syncthreads();
            if (got != 0) continue;              // L1 already inlined it

            const int b = j & (Bq - 1), sub = j >> 6, t0 = sub * SUB;
            wait_flag(g_fl0 + b, sub + 1, tid);

            const float4* src = (const float4*)(g_y0 +
                                ((size_t)b * Sq + t0) * Hq);
            for (int i = tid; i < SUB * Hq / 4; i += PT)
                cp_async16(dyn_sa + i * 16, src + i);
            CP_COMMIT(); CP_WAIT(0);
            __syncthreads();

            float* dst = g_xg1p + ((size_t)b * Sq + t0) * XGP + wr;
#pragma unroll 2
            for (int tt = 0; tt < SUB; tt++) {
                const float v = dot100(wp, dyn + tt * Hq) + bih;
                if (tid < Gq) dst[(size_t)tt * XGP] = v;
            }
            __threadfence();
            __syncthreads();
            if (tid == 0) atomicExch(&g_fl2[j], 1);
            __syncthreads();                     // protect dyn (WAR)
        }
    }

    // ---------------- G3 pool: out = y1 @ w_out^T + b_out ----------------
    {
        const int nidx = tid % 160;              // 2 groups of 160
        const int tq   = tid / 160;              // 0..1
        const int nr   = min(nidx, OUTq - 1);
        load_row100(wp, w_out + nr * Hq);
        const float bo = b_out[nr];

        for (;;) {
            if (tid == 0) js = atomicAdd(&g_jobctr, 1);
            __syncthreads();
            const int j = js;
            __syncthreads();
            if (j >= Bq * 16) break;             // 1024 jobs of 128 steps
            const int b   = j & (Bq - 1);
            const int blk = j >> 6;              // 0..15

            wait_flag(g_fl1 + b, 2 * blk + 2, tid);

            const float4* src = (const float4*)(g_y1 +
                                ((size_t)b * Sq + blk * 128) * Hq);
            for (int i = tid; i < 128 * Hq / 4; i += PT)
                cp_async16(dyn_sa + i * 16, src + i);
            CP_COMMIT(); CP_WAIT(0);
            __syncthreads();

            if (nidx < OUTq) {
                float* ob = out + ((size_t)b * Sq + blk * 128) * OUTq;
                for (int tt = tq; tt < 128; tt += 2)
                    ob[(size_t)tt * OUTq + nidx] = dot100(wp, dyn + tt * Hq) + bo;
            }
            __syncthreads();                     // protect stage (WAR)
        }
    }
}

// ---------------------------------------------------------------------------
// Launch: g1 (also resets flags) -> persistent pipeline.
// One stream, graph-capturable, no allocations.
// ---------------------------------------------------------------------------
extern "C" void kernel_launch(void* const* d_in, const int* in_sizes, int n_in,
                              void* d_out, int out_size)
{
    (void)in_sizes; (void)n_in; (void)out_size;
    const float* seq     = (const float*)d_in[0];
    const float* h0      = (const float*)d_in[1];   // [2][B][H]
    const float* w_ih_l0 = (const float*)d_in[2];
    const float* w_hh_l0 = (const float*)d_in[3];
    const float* b_ih_l0 = (const float*)d_in[4];
    const float* b_hh_l0 = (const float*)d_in[5];
    const float* w_ih_l1 = (const float*)d_in[6];
    const float* w_hh_l1 = (const float*)d_in[7];
    const float* b_ih_l1 = (const float*)d_in[8];
    const float* b_hh_l1 = (const float*)d_in[9];
    const float* w_out   = (const float*)d_in[10];
    const float* b_out   = (const float*)d_in[11];
    float* out = (float*)d_out;

    const int G1_BYTES  = SUB * INq * 4;                 // 53248
    const int DYN_BYTES = (SUB * Hq + SUB * XGP) * 4;    // 103424
    cudaFuncSetAttribute(g1_kernel,
                         cudaFuncAttributeMaxDynamicSharedMemorySize, G1_BYTES);
    cudaFuncSetAttribute(pipeline_kernel,
                         cudaFuncAttributeMaxDynamicSharedMemorySize, DYN_BYTES);

    g1_kernel<<<NJOB2, 160, G1_BYTES>>>(seq, w_ih_l0, b_ih_l0);

    pipeline_kernel<<<148, PT, DYN_BYTES>>>(
        w_hh_l0, b_hh_l0,
        w_ih_l1, b_ih_l1, w_hh_l1, b_hh_l1,
        w_out, b_out, h0, out);
}

// round 16
// speedup vs baseline: 1.6046x; 1.0251x over previous
#include <cuda_runtime.h>
#include <cstdint>

// Problem constants
#define Bq   64
#define Sq   2048
#define INq  208
#define Hq   100
#define Gq   300      // 3*H gate rows
#define OUTq 98
#define Mq   (Bq * Sq)   // 131072 rows

#define SUB   64          // handoff granularity (steps)
#define NSUB  (Sq / SUB)  // 32
#define NJOB  (Bq * NSUB) // 2048 jobs (G1 phase and G2 queue)
#define XGP   304         // padded row stride (floats, 16B-aligned)
#define PT    320         // pipeline threads (300 real + 20 pad)
#define NCTA  148         // persistent grid (== SM count)

// ---------------------------------------------------------------------------
// Scratch (static __device__ arrays — allocation is forbidden)
// ---------------------------------------------------------------------------
__device__ float g_xg0 [(size_t)Mq * Gq];   // layer-0 input gates (phase-0 out)
__device__ float g_xg1p[(size_t)Mq * XGP];  // layer-1 input gates, padded rows
__device__ float g_y0  [(size_t)Mq * Hq];   // layer-0 hidden sequence
__device__ float g_y1  [(size_t)Mq * Hq];   // layer-1 hidden sequence
__device__ int   g_fl0[Bq];                 // L0 sub-blocks done per batch
__device__ int   g_fl1[Bq];                 // L1 sub-blocks done per batch
__device__ int   g_fl2[NJOB];               // per-job xg1 ready
__device__ int   g_claim[NJOB];             // 0=free 1=worker 2=L1-inline
__device__ int   g_jobctr;                  // G3 job counter
__device__ int   g_g2ctr;                   // G2 worker job counter
__device__ int   g_phase;                   // phase-0 barrier counter

#define FMA2(c, a, b) \
    asm("fma.rn.f32x2 %0, %1, %2, %0;" : "+l"(c) : "l"(a), "l"(b))

__device__ __forceinline__ void cp_async4(uint32_t saddr, const float* gptr) {
    asm volatile("cp.async.ca.shared.global [%0], [%1], 4;"
                 :: "r"(saddr), "l"(gptr));
}
__device__ __forceinline__ void cp_async16(uint32_t saddr, const void* gptr) {
    asm volatile("cp.async.cg.shared.global [%0], [%1], 16;"
                 :: "r"(saddr), "l"(gptr));
}
#define CP_COMMIT()  asm volatile("cp.async.commit_group;" ::: "memory")
#define CP_WAIT(n)   asm volatile("cp.async.wait_group %0;" :: "n"(n) : "memory")

__device__ __forceinline__ float tanh_hw(float x) {
    float y;
    asm("tanh.approx.f32 %0, %1;" : "=f"(y) : "f"(x));
    return y;
}

// ---------------------------------------------------------------------------
// Packed-dot helpers
// ---------------------------------------------------------------------------
__device__ __forceinline__ void load_row100(unsigned long long* wp,
                                            const float* row) {
    const float4* r4 = (const float4*)row;
#pragma unroll
    for (int q = 0; q < 25; q++) {
        const float4 v = __ldg(r4 + q);
        asm("mov.b64 %0, {%1, %2};" : "=l"(wp[2 * q])     : "f"(v.x), "f"(v.y));
        asm("mov.b64 %0, {%1, %2};" : "=l"(wp[2 * q + 1]) : "f"(v.z), "f"(v.w));
    }
}

__device__ __forceinline__ float dot100(const unsigned long long* wp,
                                        const float* vec) {
    const ulonglong2* hp = (const ulonglong2*)vec;
    unsigned long long a0 = 0ull, a1 = 0ull, a2 = 0ull, a3 = 0ull;
#pragma unroll
    for (int q = 0; q < 25; q++) {
        const ulonglong2 hv = hp[q];
        if (q & 1) { FMA2(a1, wp[2 * q], hv.x); FMA2(a3, wp[2 * q + 1], hv.y); }
        else       { FMA2(a0, wp[2 * q], hv.x); FMA2(a2, wp[2 * q + 1], hv.y); }
    }
    unsigned long long s01, s23, ssum;
    asm("add.rn.f32x2 %0, %1, %2;" : "=l"(s01)  : "l"(a0),  "l"(a1));
    asm("add.rn.f32x2 %0, %1, %2;" : "=l"(s23)  : "l"(a2),  "l"(a3));
    asm("add.rn.f32x2 %0, %1, %2;" : "=l"(ssum) : "l"(s01), "l"(s23));
    float lo, hi;
    asm("mov.b64 {%0, %1}, %2;" : "=f"(lo), "=f"(hi) : "l"(ssum));
    return lo + hi;
}

// 104-wide half-row (52 packed regs)
__device__ __forceinline__ void load_row104(unsigned long long* wp,
                                            const float* row) {
    const float4* r4 = (const float4*)row;
#pragma unroll
    for (int q = 0; q < 26; q++) {
        const float4 v = __ldg(r4 + q);
        asm("mov.b64 %0, {%1, %2};" : "=l"(wp[2 * q])     : "f"(v.x), "f"(v.y));
        asm("mov.b64 %0, {%1, %2};" : "=l"(wp[2 * q + 1]) : "f"(v.z), "f"(v.w));
    }
}

__device__ __forceinline__ float dot104(const unsigned long long* wp,
                                        const float* vec) {
    const ulonglong2* hp = (const ulonglong2*)vec;
    unsigned long long a0 = 0ull, a1 = 0ull, a2 = 0ull, a3 = 0ull;
#pragma unroll
    for (int q = 0; q < 26; q++) {
        const ulonglong2 hv = hp[q];
        if (q & 1) { FMA2(a1, wp[2 * q], hv.x); FMA2(a3, wp[2 * q + 1], hv.y); }
        else       { FMA2(a0, wp[2 * q], hv.x); FMA2(a2, wp[2 * q + 1], hv.y); }
    }
    unsigned long long s01, s23, ssum;
    asm("add.rn.f32x2 %0, %1, %2;" : "=l"(s01)  : "l"(a0),  "l"(a1));
    asm("add.rn.f32x2 %0, %1, %2;" : "=l"(s23)  : "l"(a2),  "l"(a3));
    asm("add.rn.f32x2 %0, %1, %2;" : "=l"(ssum) : "l"(s01), "l"(s23));
    float lo, hi;
    asm("mov.b64 {%0, %1}, %2;" : "=f"(lo), "=f"(hi) : "l"(ssum));
    return lo + hi;
}

// ---------------------------------------------------------------------------
// Flag reset
// ---------------------------------------------------------------------------
__global__ void zero_flags() {
    const int g = blockIdx.x * blockDim.x + threadIdx.x;
    const int stride = gridDim.x * blockDim.x;
    for (int i = g; i < NJOB; i += stride) { g_claim[i] = 0; g_fl2[i] = 0; }
    if (g < Bq) { g_fl0[g] = 0; g_fl1[g] = 0; }
    if (g == Bq) { g_jobctr = 0; g_g2ctr = 0; g_phase = 0; }
}

// ---------------------------------------------------------------------------
// Scan SMEM (all arrays indexable by all PT threads -> guard-free matvec)
// ---------------------------------------------------------------------------
struct GruSmem {
    float h[2][128];        // units 0..99 real
    float hg[PT];           // rows 0..299 real
    float ring[4][PT];      // xg staging ring
};

// gate nonlinearity via HW tanh (validated: rel_err ~5.7e-6)
__device__ __forceinline__ void gate_math(
    int t, int cur, int tid, int jc, GruSmem* s,
    const float* __restrict__ xgp, float* __restrict__ y_b)
{
    const float xr = xgp[jc], xz = xgp[Hq + jc], xn = xgp[2 * Hq + jc];
    const float hr = s->hg[jc];
    const float hz = s->hg[Hq + jc];
    const float hn = s->hg[2 * Hq + jc];
    const float hprev = s->h[cur][jc];
    const float r  = 0.5f * tanh_hw(0.5f * (xr + hr)) + 0.5f;
    const float z  = 0.5f * tanh_hw(0.5f * (xz + hz)) + 0.5f;
    const float nt = tanh_hw(xn + r * hn);
    const float hnew = (1.f - z) * nt + z * hprev;
    s->h[cur ^ 1][tid] = hnew;
    if (tid < Hq) y_b[(size_t)t * Hq + tid] = hnew;
}

// Ring-streaming GRU step: xg prefetched from gmem (stride/clamp params let
// L0 stream xg0 rows and L1 stream padded xg1p rows within a sub).
__device__ __forceinline__ void gru_step_ring(
    int t, int cur, int tid, int jc, int wr,
    GruSmem* s, uint32_t ring_sa,
    const unsigned long long* wp, float bhh,
    const float* __restrict__ xg_base, int stride, int rmax,
    float* __restrict__ y_b)
{
    const int r = min(t + 3, rmax);
    cp_async4(ring_sa + (((t + 3) & 3) * PT + tid) * 4,
              xg_base + (size_t)r * stride + wr);
    CP_COMMIT();

    s->hg[tid] = dot100(wp, s->h[cur]) + bhh;    // uniform, all PT threads
    __syncthreads();                             // A: hg complete

    if (tid < 128) gate_math(t, cur, tid, jc, s, &s->ring[t & 3][0], y_b);
    CP_WAIT(2);                                  // ring slot t+1 landed
    __syncthreads();                             // B: publish
}

// SMEM-xg GRU step (L1 inline path; xg_sub rows padded to XGP)
__device__ __forceinline__ void gru_step_smem(
    int t, int cur, int tid, int jc,
    GruSmem* s,
    const unsigned long long* wp, float bhh,
    const float* __restrict__ xg_sub,
    float* __restrict__ y_b)
{
    s->hg[tid] = dot100(wp, s->h[cur]) + bhh;
    __syncthreads();                             // A
    if (tid < 128)
        gate_math(t, cur, tid, jc, s, xg_sub + (t & (SUB - 1)) * XGP, y_b);
    __syncthreads();                             // B
}

// stage 3 ring rows t0..t0+2 (clamped); leaves <=2 groups pending
__device__ __forceinline__ void ring_prologue(
    uint32_t ring_sa, const float* xg_base, int stride, int t0, int rmax,
    int tid, int wr)
{
#pragma unroll
    for (int p = 0; p < 3; p++) {
        cp_async4(ring_sa + (((t0 + p) & 3) * PT + tid) * 4,
                  xg_base + (size_t)min(t0 + p, rmax) * stride + wr);
        CP_COMMIT();
    }
    CP_WAIT(2);
    __syncthreads();
}

__device__ __forceinline__ void wait_flag(volatile int* f, int target, int tid) {
    if (tid == 0) {
        while (*f < target) __nanosleep(128);
    }
    __syncthreads();
    __threadfence();                             // acquire
}

// G1 compute for one (b,sub): stage seq -> xg_sub[SUB][XGP] in SMEM.
// Two 104-wide K-half passes (R13-validated code path, bit-identical order).
__device__ __forceinline__ void g1_compute(
    int b, int t0, int tid, int wr, int col,
    float* __restrict__ seqstage, float* __restrict__ xg_sub,
    uint32_t dyn_sa,
    const float* __restrict__ seq,
    const float* __restrict__ w_ih, const float* __restrict__ b_ih)
{
    const float4* src = (const float4*)(seq + ((size_t)b * Sq + t0) * INq);
    for (int i = tid; i < SUB * INq / 4; i += PT)
        cp_async16(dyn_sa + i * 16, src + i);
    CP_COMMIT(); CP_WAIT(0);
    __syncthreads();

    unsigned long long wpl[52];
    load_row104(wpl, w_ih + wr * INq);
#pragma unroll 2
    for (int tt = 0; tt < SUB; tt++)
        xg_sub[tt * XGP + col] = dot104(wpl, seqstage + tt * INq);

    load_row104(wpl, w_ih + wr * INq + 104);
    const float bias = b_ih[wr];
#pragma unroll 2
    for (int tt = 0; tt < SUB; tt++)
        xg_sub[tt * XGP + col] += dot104(wpl, seqstage + tt * INq + 104) + bias;
    __syncthreads();
}

// ---------------------------------------------------------------------------
// Persistent pipeline: 148 CTAs x PT threads (all co-resident).
//   Phase 0 (ALL CTAs): static partition of the 2048 G1 jobs; each CTA
//     computes its jobs into SMEM and stores to g_xg0 (unpadded). Then a
//     flag barrier (safe: full co-residency by construction).
//   Then exactly the R15 pipeline:
//     CTA 0..63    : L0 scan (ring from g_xg0) -> G2 queue -> G3
//     CTA 64..127  : L1 claim-or-consume G2 -> G3
//     CTA 128..147 : G2 workers -> G3 pool
// Dyn SMEM 131072B: phase0 [seqstage 64*208 | xg_sub 64*304];
//                   pipeline [ystage 64*100 | xg_sub 64*304]
// ---------------------------------------------------------------------------
__global__ __launch_bounds__(PT, 1) void pipeline_kernel(
    const float* __restrict__ seq,
    const float* __restrict__ w_ih_l0, const float* __restrict__ b_ih_l0,
    const float* __restrict__ w_hh_l0, const float* __restrict__ b_hh_l0,
    const float* __restrict__ w_ih_l1, const float* __restrict__ b_ih_l1,
    const float* __restrict__ w_hh_l1, const float* __restrict__ b_hh_l1,
    const float* __restrict__ w_out,   const float* __restrict__ b_out,
    const float* __restrict__ h0,      float* __restrict__ out)
{
    extern __shared__ __align__(16) float dyn[];
    __shared__ __align__(16) GruSmem s;
    __shared__ int js, cls;

    const int tid  = threadIdx.x;
    const int role = blockIdx.x;
    const int wr   = min(tid, Gq - 1);
    const int jc   = min(tid, Hq - 1);
    const int col  = min(tid, XGP - 1);
    const uint32_t ring_sa = (uint32_t)__cvta_generic_to_shared(&s.ring[0][0]);
    const uint32_t dyn_sa  = (uint32_t)__cvta_generic_to_shared(dyn);

    // ================= Phase 0: full-chip G1 =================
    {
        float* seqstage = dyn;                   // [SUB*INq]
        float* xg_sub   = dyn + SUB * INq;       // [SUB][XGP]
        for (int j = role; j < NJOB; j += NCTA) {
            const int b  = j & (Bq - 1);
            const int t0 = (j >> 6) * SUB;
            g1_compute(b, t0, tid, wr, col, seqstage, xg_sub, dyn_sa,
                       seq, w_ih_l0, b_ih_l0);
            // store to unpadded g_xg0 (coalesced per row)
            if (tid < Gq) {
                float* dst = g_xg0 + ((size_t)b * Sq + t0) * Gq + tid;
#pragma unroll 2
                for (int tt = 0; tt < SUB; tt++)
                    dst[(size_t)tt * Gq] = xg_sub[tt * XGP + tid];
            }
            __syncthreads();                     // protect xg_sub (WAR)
        }
        // global barrier (all 148 CTAs co-resident -> safe)
        __threadfence();
        __syncthreads();
        if (tid == 0) {
            atomicAdd(&g_phase, 1);
            while (*(volatile int*)&g_phase < NCTA) __nanosleep(256);
        }
        __syncthreads();
        __threadfence();
    }

    // ================= R15 pipeline (unchanged) =================
    unsigned long long wp[50];
    bool do_g2_queue = (role >= 2 * Bq);

    if (role < Bq) {
        // ---------------- L0 scan ----------------
        const int b = role;
        load_row100(wp, w_hh_l0 + wr * Hq);
        const float bhh = b_hh_l0[wr];
        if (tid < Hq) s.h[0][tid] = h0[b * Hq + tid];
        const float* xg_b = g_xg0 + (size_t)b * Sq * Gq;
        float*       y_b  = g_y0  + (size_t)b * Sq * Hq;
        __syncthreads();

        ring_prologue(ring_sa, xg_b, Gq, 0, Sq - 1, tid, wr);

        for (int t = 0; t < Sq; t += 2) {
            gru_step_ring(t,     0, tid, jc, wr, &s, ring_sa, wp, bhh,
                          xg_b, Gq, Sq - 1, y_b);
            gru_step_ring(t + 1, 1, tid, jc, wr, &s, ring_sa, wp, bhh,
                          xg_b, Gq, Sq - 1, y_b);
            if (((t + 2) & (SUB - 1)) == 0) {
                __threadfence();
                __syncthreads();
                if (tid == 0) atomicExch(g_fl0 + b, (t + 2) / SUB);
            }
        }
        do_g2_queue = true;                      // help finish G2, then G3
    } else if (role < 2 * Bq) {
        // ---------------- L1 ----------------
        const int b = role - Bq;
        const float* y0_b  = g_y0 + (size_t)b * Sq * Hq;
        float*       y1_b  = g_y1 + (size_t)b * Sq * Hq;
        const float* xgp_b = g_xg1p + (size_t)b * Sq * XGP;
        float* ystage = dyn;                     // [SUB*Hq]
        float* xg_sub = dyn + SUB * Hq;          // [SUB][XGP]
        if (tid < Hq) s.h[0][tid] = h0[Bq * Hq + b * Hq + tid];
        __syncthreads();

        load_row100(wp, w_hh_l1 + wr * Hq);
        float bhh = b_hh_l1[wr];

        for (int sub = 0; sub < NSUB; sub++) {
            const int t0 = sub * SUB;
            const int j  = sub * Bq + b;

            if (tid == 0) cls = atomicCAS(&g_claim[j], 0, 2);
            __syncthreads();
            const int owner = cls;
            __syncthreads();

            if (owner == 0) {
                // inline: stage y0 -> compute G2 into SMEM -> scan from SMEM
                wait_flag(g_fl0 + b, sub + 1, tid);
                const float4* src = (const float4*)(y0_b + (size_t)t0 * Hq);
                for (int i = tid; i < SUB * Hq / 4; i += PT)
                    cp_async16(dyn_sa + i * 16, src + i);
                CP_COMMIT(); CP_WAIT(0);
                __syncthreads();

                load_row100(wp, w_ih_l1 + wr * Hq);
                const float bih = b_ih_l1[wr];
#pragma unroll 2
                for (int tt = 0; tt < SUB; tt++)
                    xg_sub[tt * XGP + col] = dot100(wp, ystage + tt * Hq) + bih;
                __syncthreads();

                load_row100(wp, w_hh_l1 + wr * Hq);
                for (int t = t0; t < t0 + SUB; t += 2) {
                    gru_step_smem(t,     0, tid, jc, &s, wp, bhh, xg_sub, y1_b);
                    gru_step_smem(t + 1, 1, tid, jc, &s, wp, bhh, xg_sub, y1_b);
                }
            } else {
                // consume: ring-stream worker-made xg1p (no block copy)
                wait_flag(g_fl2 + j, 1, tid);
                ring_prologue(ring_sa, xgp_b, XGP, t0, t0 + SUB - 1, tid, wr);
                for (int t = t0; t < t0 + SUB; t += 2) {
                    gru_step_ring(t,     0, tid, jc, wr, &s, ring_sa, wp, bhh,
                                  xgp_b, XGP, t0 + SUB - 1, y1_b);
                    gru_step_ring(t + 1, 1, tid, jc, wr, &s, ring_sa, wp, bhh,
                                  xgp_b, XGP, t0 + SUB - 1, y1_b);
                }
            }
            __threadfence();
            __syncthreads();
            if (tid == 0) atomicExch(g_fl1 + b, sub + 1);
        }
    }

    // ---------------- G2 queue (workers from start; L0 CTAs after scan) ----
    if (do_g2_queue) {
        load_row100(wp, w_ih_l1 + wr * Hq);
        const float bih = b_ih_l1[wr];

        for (;;) {
            if (tid == 0) js = atomicAdd(&g_g2ctr, 1);
            __syncthreads();
            const int j = js;
            __syncthreads();
            if (j >= NJOB) break;

            if (tid == 0) cls = atomicCAS(&g_claim[j], 0, 1);
            __syncthreads();
            const int got = cls;
            __syncthreads();
            if (got != 0) continue;              // L1 already inlined it

            const int b = j & (Bq - 1), sub = j >> 6, t0 = sub * SUB;
            wait_flag(g_fl0 + b, sub + 1, tid);

            const float4* src = (const float4*)(g_y0 +
                                ((size_t)b * Sq + t0) * Hq);
            for (int i = tid; i < SUB * Hq / 4; i += PT)
                cp_async16(dyn_sa + i * 16, src + i);
            CP_COMMIT(); CP_WAIT(0);
            __syncthreads();

            float* dst = g_xg1p + ((size_t)b * Sq + t0) * XGP + wr;
#pragma unroll 2
            for (int tt = 0; tt < SUB; tt++) {
                const float v = dot100(wp, dyn + tt * Hq) + bih;
                if (tid < Gq) dst[(size_t)tt * XGP] = v;
            }
            __threadfence();
            __syncthreads();
            if (tid == 0) atomicExch(&g_fl2[j], 1);
            __syncthreads();                     // protect dyn (WAR)
        }
    }

    // ---------------- G3 pool: out = y1 @ w_out^T + b_out ----------------
    {
        const int nidx = tid % 160;              // 2 groups of 160
        const int tq   = tid / 160;              // 0..1
        const int nr   = min(nidx, OUTq - 1);
        load_row100(wp, w_out + nr * Hq);
        const float bo = b_out[nr];

        for (;;) {
            if (tid == 0) js = atomicAdd(&g_jobctr, 1);
            __syncthreads();
            const int j = js;
            __syncthreads();
            if (j >= Bq * 16) break;             // 1024 jobs of 128 steps
            const int b   = j & (Bq - 1);
            const int blk = j >> 6;              // 0..15

            wait_flag(g_fl1 + b, 2 * blk + 2, tid);

            const float4* src = (const float4*)(g_y1 +
                                ((size_t)b * Sq + blk * 128) * Hq);
            for (int i = tid; i < 128 * Hq / 4; i += PT)
                cp_async16(dyn_sa + i * 16, src + i);
            CP_COMMIT(); CP_WAIT(0);
            __syncthreads();

            if (nidx < OUTq) {
                float* ob = out + ((size_t)b * Sq + blk * 128) * OUTq;
                for (int tt = tq; tt < 128; tt += 2)
                    ob[(size_t)tt * OUTq + nidx] = dot100(wp, dyn + tt * Hq) + bo;
            }
            __syncthreads();                     // protect stage (WAR)
        }
    }
}

// ---------------------------------------------------------------------------
// Launch: zero_flags -> persistent pipeline (G1 phase inside).
// One stream, graph-capturable, no allocations.
// ---------------------------------------------------------------------------
extern "C" void kernel_launch(void* const* d_in, const int* in_sizes, int n_in,
                              void* d_out, int out_size)
{
    (void)in_sizes; (void)n_in; (void)out_size;
    const float* seq     = (const float*)d_in[0];
    const float* h0      = (const float*)d_in[1];   // [2][B][H]
    const float* w_ih_l0 = (const float*)d_in[2];
    const float* w_hh_l0 = (const float*)d_in[3];
    const float* b_ih_l0 = (const float*)d_in[4];
    const float* b_hh_l0 = (const float*)d_in[5];
    const float* w_ih_l1 = (const float*)d_in[6];
    const float* w_hh_l1 = (const float*)d_in[7];
    const float* b_ih_l1 = (const float*)d_in[8];
    const float* b_hh_l1 = (const float*)d_in[9];
    const float* w_out   = (const float*)d_in[10];
    const float* b_out   = (const float*)d_in[11];
    float* out = (float*)d_out;

    const int DYN_BYTES = (SUB * INq + SUB * XGP) * 4;   // 131072
    cudaFuncSetAttribute(pipeline_kernel,
                         cudaFuncAttributeMaxDynamicSharedMemorySize,
                         DYN_BYTES);

    zero_flags<<<16, 256>>>();

    pipeline_kernel<<<NCTA, PT, DYN_BYTES>>>(
        seq, w_ih_l0, b_ih_l0, w_hh_l0, b_hh_l0,
        w_ih_l1, b_ih_l1, w_hh_l1, b_hh_l1,
        w_out, b_out, h0, out);
}